// round 16
// baseline (speedup 1.0000x reference)
#include <cuda_runtime.h>
#include <cstdint>

// Conv2D: x[4096,4096] fp32, w[15,15], valid -> out[4082,4082] + bias.
//
// Round 16 = Round 15 geometry + dependency-latency fix.
//  R12-R15 invariant: tensor ~43% regardless of occ/L1 -> limiter is the
//  serial 3-HMMA accumulator chain per n-tile, pinned by asm volatile.
//  Fix: load ALL 10 A chunks per ky, then issue s-outer/j-inner: 3 groups
//  of 8 INDEPENDENT HMMAs (dependent d[j] reuse now 8 instrs apart).
//  Also drop volatile/memory-clobber on mma (register-only op).
//
//  - CTA = 4 warps 2x2 -> 32x128 tile; warp tile 16x64 (8 n-tiles).
//  - One B set per ky shared by all n-tiles (band shift-invariance).
//  - XP=148 (==20 mod 32): fragment LDS conflict-free ({20g+e} permutes).
//  - Fused tf32 convert in staging; float2 stores (rows 8B-aligned).

typedef unsigned int u32;

#define HI 4096
#define WI 4096
#define KH 15
#define KW 15
#define OH 4082
#define OW 4082

#define NT  128
#define CTAY 32
#define CTAX 128
#define XR  (CTAY + KH - 1)   // 46 staged rows
#define XQ  36                // float4 per row (144 cols >= 143 needed)
#define XP  148               // pitch (floats); 148 % 32 == 20 -> conflict-free

static __device__ __forceinline__ u32 f2tf(float f) {
    u32 r; asm("cvt.rna.tf32.f32 %0, %1;" : "=r"(r) : "f"(f)); return r;
}

__global__ __launch_bounds__(NT, 5)
void conv2d_hmma5_kernel(const float* __restrict__ x, const float* __restrict__ w,
                         const float* __restrict__ bias, float* __restrict__ out)
{
    __shared__ u32 s_X[XR * XP];       // 27232 B, tf32-converted X tile
    __shared__ u32 s_B[KH * 24 * 8];   // 11520 B, banded B per ky, [c][n]

    const int tid  = threadIdx.x;
    const int wid  = tid >> 5;
    const int lane = tid & 31;
    const int g  = lane >> 2;           // 0..7
    const int e  = lane & 3;            // 0..3
    const int wy = wid >> 1;            // 0..1  warp row in CTA
    const int wx = wid & 1;             // 0..1  warp col in CTA
    const int ox0 = blockIdx.x * CTAX;
    const int oy0 = blockIdx.y * CTAY;

    // ---- Build banded B (tf32) for all 15 ky: B[c,n] = W[ky, c-n] ----
    for (int i = tid; i < KH * 24 * 8; i += NT) {
        const int ky = i / 192, r = i - ky * 192;
        const int c = r >> 3, n = r & 7;
        const int kx = c - n;
        s_B[i] = (kx >= 0 && kx < KW) ? f2tf(w[ky * KW + kx]) : 0u;
    }

    // ---- Stage X tile (46 x 144) with fused tf32 convert ----
    for (int i = tid; i < XR * XQ; i += NT) {
        const int r = i / XQ, q = i - r * XQ;
        const int gy = oy0 + r, gx = ox0 + 4 * q;
        uint4 t = make_uint4(0u, 0u, 0u, 0u);
        if (gy < HI && gx < WI) {       // gx mult of 4, WI%4==0 -> full float4
            const float4 v = __ldg(reinterpret_cast<const float4*>(&x[(long)gy * WI + gx]));
            t = make_uint4(f2tf(v.x), f2tf(v.y), f2tf(v.z), f2tf(v.w));
        }
        *reinterpret_cast<uint4*>(&s_X[r * XP + 4 * q]) = t;
    }
    __syncthreads();

    float d[8][4];
    #pragma unroll
    for (int j = 0; j < 8; ++j)
        #pragma unroll
        for (int k = 0; k < 4; ++k) d[j][k] = 0.f;

    const int rowb = (wy << 4) + g;     // warp oy strip + fragment row
    const int colb = (wx << 6);         // warp col base within staged tile

    // ---- Main loop: 15 ky, 24 HMMA each, s-outer (8-way independent) ----
    #pragma unroll 1
    for (int ky = 0; ky < KH; ++ky) {
        const u32* r0 = &s_X[(rowb + ky) * XP + colb];
        const u32* r1 = r0 + 8 * XP;

        const u32* Bk = &s_B[ky * 192];
        u32 B[3][2];
        #pragma unroll
        for (int s = 0; s < 3; ++s) {   // B chunk s covers c' = 8s..8s+7
            B[s][0] = Bk[(8 * s + e) * 8 + g];
            B[s][1] = Bk[(8 * s + e + 4) * 8 + g];
        }

        u32 A[10][4];                   // ALL chunks for this ky (cols 8t..8t+7)
        #pragma unroll
        for (int t = 0; t < 10; ++t) {
            A[t][0] = r0[8 * t + e];     A[t][1] = r1[8 * t + e];
            A[t][2] = r0[8 * t + e + 4]; A[t][3] = r1[8 * t + e + 4];
        }

        #pragma unroll
        for (int s = 0; s < 3; ++s)     // groups of 8 INDEPENDENT HMMAs
            #pragma unroll
            for (int j = 0; j < 8; ++j)
                asm("mma.sync.aligned.m16n8k8.row.col.f32.tf32.tf32.f32 "
                    "{%0,%1,%2,%3}, {%4,%5,%6,%7}, {%8,%9}, {%0,%1,%2,%3};"
                    : "+f"(d[j][0]), "+f"(d[j][1]), "+f"(d[j][2]), "+f"(d[j][3])
                    : "r"(A[j+s][0]), "r"(A[j+s][1]), "r"(A[j+s][2]), "r"(A[j+s][3]),
                      "r"(B[s][0]), "r"(B[s][1]));
    }

    // ---- Epilogue: bias + float2 stores (out rows only 8B-aligned) ----
    const float b = __ldg(&bias[0]);
    const int oyA = oy0 + rowb;
    const int oyB = oyA + 8;
    #pragma unroll
    for (int j = 0; j < 8; ++j) {
        const int ox = ox0 + colb + 8 * j + 2 * e;
        if (ox + 1 < OW) {              // ox even, OW even -> no straddle
            if (oyA < OH)
                *reinterpret_cast<float2*>(&out[(long)oyA * OW + ox]) =
                    make_float2(d[j][0] + b, d[j][1] + b);
            if (oyB < OH)
                *reinterpret_cast<float2*>(&out[(long)oyB * OW + ox]) =
                    make_float2(d[j][2] + b, d[j][3] + b);
        }
    }
}

extern "C" void kernel_launch(void* const* d_in, const int* in_sizes, int n_in,
                              void* d_out, int out_size)
{
    const float* x    = (const float*)d_in[0];
    const float* w    = (const float*)d_in[1];
    const float* bias = (const float*)d_in[2];
    float* out        = (float*)d_out;

    dim3 grid((OW + CTAX - 1) / CTAX,   // 32
              (OH + CTAY - 1) / CTAY);  // 128
    conv2d_hmma5_kernel<<<grid, NT>>>(x, w, bias, out);
}

// round 17
// speedup vs baseline: 1.4743x; 1.4743x over previous
#include <cuda_runtime.h>
#include <cuda_fp16.h>
#include <cstdint>

// Conv2D: x[4096,4096] fp32, w[15,15], valid -> out[4082,4082] + bias.
//
// Round 17: fp16 m16n8k16 banded-B conv — 2/3 the MMA instructions of the
// tf32 k8 version (R12-R16 showed dur tracks HMMA count only).
// fp16 mantissa (11 bits) == tf32 mantissa -> same rel_err ~3e-4.
//  - Per ky, n-tile j (8 outputs) = 2 k16 HMMAs on A chunks (j>>1)+s.
//  - Two banded B variants (even/odd j alignment): B[k,n] = W[ky, k-8*var-n].
//  - X staged as packed f16x2, pitch 84 u32 (==20 mod 32 -> A fragment LDS
//    conflict-free); B layout [c2][n] (banks 8e+g permute -> conflict-free).
//  - CTA 4 warps 2x2 -> 32x128 tile; warp 16x64; 6 CTAs/SM.

typedef unsigned int u32;

#define HI 4096
#define WI 4096
#define KH 15
#define KW 15
#define OH 4082
#define OW 4082

#define NT  128
#define CTAY 32
#define CTAX 128
#define XR   (CTAY + KH - 1)  // 46 staged rows
#define XP2  84               // pitch in u32 (f16 pairs); 84 % 32 == 20
#define XQ8  18               // 8-col groups per row (144 cols)

__global__ __launch_bounds__(NT, 6)
void conv2d_hmma6_kernel(const float* __restrict__ x, const float* __restrict__ w,
                         const float* __restrict__ bias, float* __restrict__ out)
{
    __shared__ u32 s_X[XR * XP2];          // 15456 B: X as f16x2 pairs
    __shared__ u32 s_B[KH * 2 * 16 * 8];   // 15360 B: banded B, [ky][var][c2][n]

    const int tid  = threadIdx.x;
    const int wid  = tid >> 5;
    const int lane = tid & 31;
    const int g  = lane >> 2;              // 0..7
    const int e  = lane & 3;               // 0..3
    const int wy = wid >> 1;               // warp row (0..1)
    const int wx = wid & 1;                // warp col (0..1)
    const int ox0 = blockIdx.x * CTAX;
    const int oy0 = blockIdx.y * CTAY;

    // ---- Build banded B (f16) : B[ky][var][k=2*c2+{0,1}][n] = W[ky, k-8*var-n] ----
    for (int i = tid; i < KH * 256; i += NT) {
        const int ky = i >> 8, r = i & 255;
        const int var = r >> 7, c2 = (r >> 3) & 15, n = r & 7;
        const int kx0 = 2 * c2 - 8 * var - n;
        const float h0 = ((unsigned)kx0 < (unsigned)KW) ? w[ky * KW + kx0] : 0.f;
        const float h1 = ((unsigned)(kx0 + 1) < (unsigned)KW) ? w[ky * KW + kx0 + 1] : 0.f;
        const __half2 hh = __floats2half2_rn(h0, h1);
        s_B[ky * 256 + var * 128 + c2 * 8 + n] = *reinterpret_cast<const u32*>(&hh);
    }

    // ---- Stage X tile (46 x 144 cols) as f16x2 pairs ----
    for (int i = tid; i < XR * XQ8; i += NT) {
        const int r = i / XQ8, q = i - r * XQ8;     // 8 cols per step
        const int gy = oy0 + r, gx = ox0 + 8 * q;
        uint4 t = make_uint4(0u, 0u, 0u, 0u);
        if (gy < HI && gx < WI) {   // gx mult of 8, WI%8==0 -> all 8 in range
            const float4 v0 = __ldg(reinterpret_cast<const float4*>(&x[(long)gy * WI + gx]));
            const float4 v1 = __ldg(reinterpret_cast<const float4*>(&x[(long)gy * WI + gx + 4]));
            __half2 h0 = __floats2half2_rn(v0.x, v0.y);
            __half2 h1 = __floats2half2_rn(v0.z, v0.w);
            __half2 h2 = __floats2half2_rn(v1.x, v1.y);
            __half2 h3 = __floats2half2_rn(v1.z, v1.w);
            t = make_uint4(*reinterpret_cast<u32*>(&h0), *reinterpret_cast<u32*>(&h1),
                           *reinterpret_cast<u32*>(&h2), *reinterpret_cast<u32*>(&h3));
        }
        *reinterpret_cast<uint4*>(&s_X[r * XP2 + 4 * q]) = t;
    }
    __syncthreads();

    float d[8][4];
    #pragma unroll
    for (int j = 0; j < 8; ++j)
        #pragma unroll
        for (int k = 0; k < 4; ++k) d[j][k] = 0.f;

    const int rowb  = (wy << 4) + g;       // fragment row within staged tile
    const int colb2 = wx << 5;             // warp col base in u32 pairs (64 cols)

    // ---- Main loop: 15 ky, 16 HMMA (k16) each ----
    #pragma unroll 1
    for (int ky = 0; ky < KH; ++ky) {
        const u32* r0 = &s_X[(rowb + ky) * XP2 + colb2];
        const u32* r1 = r0 + 8 * XP2;

        u32 A[5][4];                       // chunk t: cols 16t..16t+15
        #pragma unroll
        for (int t = 0; t < 5; ++t) {
            A[t][0] = r0[8 * t + e];       A[t][1] = r1[8 * t + e];
            A[t][2] = r0[8 * t + e + 4];   A[t][3] = r1[8 * t + e + 4];
        }

        const u32* Bk = &s_B[ky * 256];
        u32 Bv[2][2][2];                   // [var][s][b0/b1]
        #pragma unroll
        for (int var = 0; var < 2; ++var)
            #pragma unroll
            for (int s = 0; s < 2; ++s) {
                Bv[var][s][0] = Bk[var * 128 + (8 * s + e) * 8 + g];
                Bv[var][s][1] = Bk[var * 128 + (8 * s + e + 4) * 8 + g];
            }

        #pragma unroll
        for (int s = 0; s < 2; ++s)        // 2 groups of 8 independent HMMAs
            #pragma unroll
            for (int j = 0; j < 8; ++j) {
                const int t = (j >> 1) + s;
                const int var = j & 1;
                asm("mma.sync.aligned.m16n8k16.row.col.f32.f16.f16.f32 "
                    "{%0,%1,%2,%3}, {%4,%5,%6,%7}, {%8,%9}, {%0,%1,%2,%3};"
                    : "+f"(d[j][0]), "+f"(d[j][1]), "+f"(d[j][2]), "+f"(d[j][3])
                    : "r"(A[t][0]), "r"(A[t][1]), "r"(A[t][2]), "r"(A[t][3]),
                      "r"(Bv[var][s][0]), "r"(Bv[var][s][1]));
            }
    }

    // ---- Epilogue: bias + float2 stores (out rows only 8B-aligned) ----
    const float b = __ldg(&bias[0]);
    const int oyA = oy0 + rowb;
    const int oyB = oyA + 8;
    #pragma unroll
    for (int j = 0; j < 8; ++j) {
        const int ox = ox0 + (wx << 6) + 8 * j + 2 * e;
        if (ox + 1 < OW) {                 // ox even, OW even -> no straddle
            if (oyA < OH)
                *reinterpret_cast<float2*>(&out[(long)oyA * OW + ox]) =
                    make_float2(d[j][0] + b, d[j][1] + b);
            if (oyB < OH)
                *reinterpret_cast<float2*>(&out[(long)oyB * OW + ox]) =
                    make_float2(d[j][2] + b, d[j][3] + b);
        }
    }
}

extern "C" void kernel_launch(void* const* d_in, const int* in_sizes, int n_in,
                              void* d_out, int out_size)
{
    const float* x    = (const float*)d_in[0];
    const float* w    = (const float*)d_in[1];
    const float* bias = (const float*)d_in[2];
    float* out        = (float*)d_out;

    dim3 grid((OW + CTAX - 1) / CTAX,   // 32
              (OH + CTAY - 1) / CTAY);  // 128
    conv2d_hmma6_kernel<<<grid, NT>>>(x, w, bias, out);
}